// round 11
// baseline (speedup 1.0000x reference)
#include <cuda_runtime.h>
#include <math_constants.h>

// Problem: B=32, T=2048, D=512, fp32
//   energy[b,t]    = dot(key[b,t,:], query[b,:])
//   attention[b,t] = softmax_T(energy)[b,t]
//   out[b,d]       = sum_t attention[b,t] * value[b,t,d]
// d_out layout: out (32*512 floats) then attention (32*2048 floats)

#define B 32
#define T 2048
#define D 512
#define TSPLIT 32
#define TCHUNK (T / TSPLIT)   // 64
#define EROWS 64              // energy rows per block
#define EPAD 129              // conflict-free row stride in smem

// Scratch (no allocations allowed in kernel_launch)
__device__ float g_energy[B * T];
__device__ float g_esum[B * T / 2];   // half-row partial sums (phase-2 split)

// ---------------------------------------------------------------------------
// Kernel 1: energy[b,t] = key[b,t,:] . query[b,:]
// av_kernel's streaming structure (the 6.2 TB/s pattern): 128 threads, each
// owns one float4 column slice; q slice loaded ONCE into registers; 64 rows
// of independent LDG.128 + FMA + STS (stride-129 smem). Reduction entirely
// after the load loop: each row's 128 partials summed by TWO threads (64-long
// chains), combined at the end.
// ---------------------------------------------------------------------------
__global__ void __launch_bounds__(128) energy_kernel(
        const float* __restrict__ query,
        const float* __restrict__ key,
        float* __restrict__ energy) {
    int blk = blockIdx.x;            // 0..1023
    int row0 = blk * EROWS;          // global row = b*T + t (same batch: 64|T)
    int b = row0 >> 11;              // T = 2048
    int tid = threadIdx.x;           // 0..127

    __shared__ float part[EROWS * EPAD];
    __shared__ float half[EROWS * 2];

    // Own q slice, loaded once (L1/L2-hot: q is 64 KB total).
    float4 qv = ((const float4*)(query + (size_t)b * D))[tid];

    const float4* k0 = (const float4*)(key + (size_t)row0 * D);

#pragma unroll 8
    for (int r = 0; r < EROWS; r++) {
        float4 kv = k0[(size_t)r * (D / 4) + tid];
        part[r * EPAD + tid] =
            kv.x * qv.x + kv.y * qv.y + kv.z * qv.z + kv.w * qv.w;
    }
    __syncthreads();

    // Phase 2a: all 128 threads; thread (h*64 + r) sums half h of row r.
    {
        int r = tid & 63;
        int h = tid >> 6;            // 0 or 1
        const float* p = part + r * EPAD + h * 64;
        float s = 0.0f;
#pragma unroll
        for (int i = 0; i < 64; i++)
            s += p[i];
        half[r * 2 + h] = s;
    }
    __syncthreads();

    // Phase 2b: threads 0..63 combine and store.
    if (tid < EROWS)
        energy[row0 + tid] = half[tid * 2] + half[tid * 2 + 1];
}

// ---------------------------------------------------------------------------
// Kernel 2: softmax over T per batch. 32 blocks x 256 threads, 8 vals/thread.
// Shuffle-based reductions: 2 barriers total.
// ---------------------------------------------------------------------------
__global__ void softmax_kernel(const float* __restrict__ energy,
                               float* __restrict__ attn) {
    int b = blockIdx.x;
    int tid = threadIdx.x;      // 0..255
    int lane = tid & 31;
    int warp = tid >> 5;        // 0..7
    __shared__ float red[8];

    const float* e = energy + (size_t)b * T;
    float vals[8];
    float m = -CUDART_INF_F;
#pragma unroll
    for (int i = 0; i < 8; i++) {
        vals[i] = e[tid + 256 * i];
        m = fmaxf(m, vals[i]);
    }
#pragma unroll
    for (int off = 16; off; off >>= 1)
        m = fmaxf(m, __shfl_xor_sync(0xFFFFFFFFu, m, off));
    if (lane == 0) red[warp] = m;
    __syncthreads();
    m = red[0];
#pragma unroll
    for (int w = 1; w < 8; w++) m = fmaxf(m, red[w]);
    __syncthreads();

    float sum = 0.0f;
#pragma unroll
    for (int i = 0; i < 8; i++) {
        vals[i] = __expf(vals[i] - m);
        sum += vals[i];
    }
#pragma unroll
    for (int off = 16; off; off >>= 1)
        sum += __shfl_xor_sync(0xFFFFFFFFu, sum, off);
    if (lane == 0) red[warp] = sum;
    __syncthreads();
    sum = red[0];
#pragma unroll
    for (int w = 1; w < 8; w++) sum += red[w];
    float inv = 1.0f / sum;

    float* arow = attn + (size_t)b * T;
#pragma unroll
    for (int i = 0; i < 8; i++)
        arow[tid + 256 * i] = vals[i] * inv;
}

// ---------------------------------------------------------------------------
// Kernel 3: out[b,:] += sum_{t in chunk ts} attn[b,t] * value[b,t,:]
// Grid (TSPLIT, B) = 1024 blocks, 128 threads; thread owns one float4 of D.
// Accumulates directly into out via REDG.
// ---------------------------------------------------------------------------
__global__ void __launch_bounds__(128) av_kernel(
        const float* __restrict__ attn,
        const float* __restrict__ value,
        float* __restrict__ out) {
    int ts = blockIdx.x;
    int b = blockIdx.y;
    int tid = threadIdx.x;  // 0..127

    __shared__ float sa[TCHUNK];
    int t0 = ts * TCHUNK;
    if (tid < TCHUNK) sa[tid] = attn[(size_t)b * T + t0 + tid];
    __syncthreads();

    const float4* v = (const float4*)(value + ((size_t)b * T + t0) * D);
    float4 acc = make_float4(0.f, 0.f, 0.f, 0.f);

#pragma unroll 8
    for (int t = 0; t < TCHUNK; t++) {
        float a = sa[t];
        float4 vv = v[(size_t)t * (D / 4) + tid];
        acc.x += a * vv.x;
        acc.y += a * vv.y;
        acc.z += a * vv.z;
        acc.w += a * vv.w;
    }

    float* o = out + (size_t)b * D + tid * 4;
    atomicAdd(o + 0, acc.x);
    atomicAdd(o + 1, acc.y);
    atomicAdd(o + 2, acc.z);
    atomicAdd(o + 3, acc.w);
}

extern "C" void kernel_launch(void* const* d_in, const int* in_sizes, int n_in,
                              void* d_out, int out_size) {
    const float* query = (const float*)d_in[0];  // [B, D]
    const float* key   = (const float*)d_in[1];  // [B, T, D]
    const float* value = (const float*)d_in[2];  // [B, T, D]

    float* out  = (float*)d_out;            // [B, D]
    float* attn = (float*)d_out + B * D;    // [B, T]

    float* energy;
    cudaGetSymbolAddress((void**)&energy, g_energy);

    // Zero the out slice (memset node — graph-capturable, no allocation).
    cudaMemsetAsync(out, 0, (size_t)B * D * sizeof(float), 0);

    // 1) energy: 1024 blocks x 128 thr, 64 rows/block (av-style streaming)
    energy_kernel<<<(B * T) / EROWS, 128>>>(query, key, energy);
    // 2) softmax -> attention slice of d_out
    softmax_kernel<<<B, 256>>>(energy, attn);
    // 3) attn @ value, accumulated straight into out
    {
        dim3 grid(TSPLIT, B);
        av_kernel<<<grid, 128>>>(attn, value, out);
    }
}

// round 12
// speedup vs baseline: 1.1994x; 1.1994x over previous
#include <cuda_runtime.h>
#include <math_constants.h>

// Problem: B=32, T=2048, D=512, fp32
//   energy[b,t]    = dot(key[b,t,:], query[b,:])
//   attention[b,t] = softmax_T(energy)[b,t]
//   out[b,d]       = sum_t attention[b,t] * value[b,t,d]
// d_out layout: out (32*512 floats) then attention (32*2048 floats)

#define B 32
#define T 2048
#define D 512
#define TSPLIT 32
#define TCHUNK (T / TSPLIT)   // 64

// Scratch (no allocations allowed in kernel_launch)
__device__ float g_energy[B * T];

// ---------------------------------------------------------------------------
// Kernel 1: energy[b,t] = key[b,t,:] . query[b,:]
// One warp per TWO consecutive rows. All 8 k-float4 loads + 4 q-float4 loads
// front-batched BEFORE any arithmetic (per-lane MLP=8 on the k stream, no
// shuffle between loads). Then two independent 5-step shuffle trees whose
// latencies overlap. 12 LDG per 2 rows vs 16 for one-row-per-warp.
// ---------------------------------------------------------------------------
__global__ void energy_kernel(const float* __restrict__ query,
                              const float* __restrict__ key,
                              float* __restrict__ energy) {
    int gw = (blockIdx.x * blockDim.x + threadIdx.x) >> 5;  // 0..B*T/2-1
    int lane = threadIdx.x & 31;
    int row0 = gw * 2;               // global row = b*T + t, even
    int b = row0 >> 11;              // T = 2048

    const float4* k0 = (const float4*)(key + (size_t)row0 * D);
    const float4* qrow = (const float4*)(query + (size_t)b * D);

    // Front-batch: 8 streaming k loads first, then 4 L1/L2-hot q loads.
    float4 ka[4], kb[4], qv[4];
#pragma unroll
    for (int i = 0; i < 4; i++) ka[i] = k0[lane + 32 * i];
#pragma unroll
    for (int i = 0; i < 4; i++) kb[i] = k0[128 + lane + 32 * i];
#pragma unroll
    for (int i = 0; i < 4; i++) qv[i] = qrow[lane + 32 * i];

    float acc0 = 0.0f, acc1 = 0.0f;
#pragma unroll
    for (int i = 0; i < 4; i++) {
        acc0 += ka[i].x * qv[i].x + ka[i].y * qv[i].y +
                ka[i].z * qv[i].z + ka[i].w * qv[i].w;
        acc1 += kb[i].x * qv[i].x + kb[i].y * qv[i].y +
                kb[i].z * qv[i].z + kb[i].w * qv[i].w;
    }

    // Two independent shuffle trees — latencies overlap.
#pragma unroll
    for (int off = 16; off; off >>= 1) {
        acc0 += __shfl_xor_sync(0xFFFFFFFFu, acc0, off);
        acc1 += __shfl_xor_sync(0xFFFFFFFFu, acc1, off);
    }

    if (lane == 0) {
        energy[row0]     = acc0;
        energy[row0 + 1] = acc1;
    }
}

// ---------------------------------------------------------------------------
// Kernel 2: softmax over T per batch. 32 blocks x 256 threads, 8 vals/thread.
// Shuffle-based reductions: 2 barriers total.
// ---------------------------------------------------------------------------
__global__ void softmax_kernel(const float* __restrict__ energy,
                               float* __restrict__ attn) {
    int b = blockIdx.x;
    int tid = threadIdx.x;      // 0..255
    int lane = tid & 31;
    int warp = tid >> 5;        // 0..7
    __shared__ float red[8];

    const float* e = energy + (size_t)b * T;
    float vals[8];
    float m = -CUDART_INF_F;
#pragma unroll
    for (int i = 0; i < 8; i++) {
        vals[i] = e[tid + 256 * i];
        m = fmaxf(m, vals[i]);
    }
#pragma unroll
    for (int off = 16; off; off >>= 1)
        m = fmaxf(m, __shfl_xor_sync(0xFFFFFFFFu, m, off));
    if (lane == 0) red[warp] = m;
    __syncthreads();
    m = red[0];
#pragma unroll
    for (int w = 1; w < 8; w++) m = fmaxf(m, red[w]);
    __syncthreads();

    float sum = 0.0f;
#pragma unroll
    for (int i = 0; i < 8; i++) {
        vals[i] = __expf(vals[i] - m);
        sum += vals[i];
    }
#pragma unroll
    for (int off = 16; off; off >>= 1)
        sum += __shfl_xor_sync(0xFFFFFFFFu, sum, off);
    if (lane == 0) red[warp] = sum;
    __syncthreads();
    sum = red[0];
#pragma unroll
    for (int w = 1; w < 8; w++) sum += red[w];
    float inv = 1.0f / sum;

    float* arow = attn + (size_t)b * T;
#pragma unroll
    for (int i = 0; i < 8; i++)
        arow[tid + 256 * i] = vals[i] * inv;
}

// ---------------------------------------------------------------------------
// Kernel 3: out[b,:] += sum_{t in chunk ts} attn[b,t] * value[b,t,:]
// Grid (TSPLIT, B) = 1024 blocks, 128 threads; thread owns one float4 of D.
// Register accumulation; REDG into out at the end.
// ---------------------------------------------------------------------------
__global__ void __launch_bounds__(128) av_kernel(
        const float* __restrict__ attn,
        const float* __restrict__ value,
        float* __restrict__ out) {
    int ts = blockIdx.x;
    int b = blockIdx.y;
    int tid = threadIdx.x;  // 0..127

    __shared__ float sa[TCHUNK];
    int t0 = ts * TCHUNK;
    if (tid < TCHUNK) sa[tid] = attn[(size_t)b * T + t0 + tid];
    __syncthreads();

    const float4* v = (const float4*)(value + ((size_t)b * T + t0) * D);
    float4 acc = make_float4(0.f, 0.f, 0.f, 0.f);

#pragma unroll 8
    for (int t = 0; t < TCHUNK; t++) {
        float a = sa[t];
        float4 vv = v[(size_t)t * (D / 4) + tid];
        acc.x += a * vv.x;
        acc.y += a * vv.y;
        acc.z += a * vv.z;
        acc.w += a * vv.w;
    }

    float* o = out + (size_t)b * D + tid * 4;
    atomicAdd(o + 0, acc.x);
    atomicAdd(o + 1, acc.y);
    atomicAdd(o + 2, acc.z);
    atomicAdd(o + 3, acc.w);
}

extern "C" void kernel_launch(void* const* d_in, const int* in_sizes, int n_in,
                              void* d_out, int out_size) {
    const float* query = (const float*)d_in[0];  // [B, D]
    const float* key   = (const float*)d_in[1];  // [B, T, D]
    const float* value = (const float*)d_in[2];  // [B, T, D]

    float* out  = (float*)d_out;            // [B, D]
    float* attn = (float*)d_out + B * D;    // [B, T]

    float* energy;
    cudaGetSymbolAddress((void**)&energy, g_energy);

    // Zero the out slice (memset node — graph-capturable, no allocation).
    cudaMemsetAsync(out, 0, (size_t)B * D * sizeof(float), 0);

    // 1) energy: one warp per 2 rows; 8 warps/block -> 4096 blocks
    energy_kernel<<<(B * T / 2) / 8, 256>>>(query, key, energy);
    // 2) softmax -> attention slice of d_out
    softmax_kernel<<<B, 256>>>(energy, attn);
    // 3) attn @ value, accumulated straight into out
    {
        dim3 grid(TSPLIT, B);
        av_kernel<<<grid, 128>>>(attn, value, out);
    }
}